// round 16
// baseline (speedup 1.0000x reference)
#include <cuda_runtime.h>
#include <cuda_bf16.h>

// Fixed-shape problem: N=2000 nodes, F=2, HIDDEN=64, K=3, G=256 graphs, E~7998 edges
#define NN    2000
#define EMAXS 8192           // max real edges supported
#define EPAD  10240          // padded capacity (E + <=1 dummy per node)
#define HID   64
#define TPB   1024

typedef unsigned long long ull;
typedef unsigned short u16;
typedef unsigned int uint32;

// ---------------- f32x2 packed-math helpers (sm_100+ PTX) ----------------
__device__ __forceinline__ ull pk2(float lo, float hi) {
    ull r; asm("mov.b64 %0,{%1,%2};" : "=l"(r) : "f"(lo), "f"(hi)); return r;
}
__device__ __forceinline__ void upk2(ull v, float& lo, float& hi) {
    asm("mov.b64 {%0,%1}, %2;" : "=f"(lo), "=f"(hi) : "l"(v));
}
__device__ __forceinline__ ull fma2v(ull a, ull b, ull c) {
    ull d; asm("fma.rn.f32x2 %0, %1, %2, %3;" : "=l"(d) : "l"(a), "l"(b), "l"(c)); return d;
}
__device__ __forceinline__ ull add2v(ull a, ull b) {
    ull d; asm("add.rn.f32x2 %0, %1, %2;" : "=l"(d) : "l"(a), "l"(b)); return d;
}

// ---------------- single fused kernel: one CTA per TWO graphs ----------------
// smem: pb0..pb3 (ulonglong2[NN]) | sedge_w f32[EPAD] | sedge_s u16[EPAD] |
//       w1d/w2q/b1s | sperm | sptr
// Node buffers: ulonglong2 per node = { graphA pair(f0,f1), graphB pair(f0,f1) }
#define SMEM_BYTES (4 * NN * 16 + EPAD * 4 + EPAD * 2 + 2048 + 2048 + 256 + NN * 4 + (NN + 1) * 4)

__global__ __launch_bounds__(TPB, 1)
void k_main(const float* __restrict__ x,
            const int* __restrict__ row, const int* __restrict__ col,
            const float* __restrict__ ew,
            const float* __restrict__ W1, const float* __restrict__ b1,
            const float* __restrict__ W2, const float* __restrict__ b2,
            float* __restrict__ out, int G, int E) {
    extern __shared__ float sm[];
    ulonglong2* pb0 = (ulonglong2*)sm;
    ulonglong2* pb1 = pb0 + NN;
    ulonglong2* pb2 = pb1 + NN;
    ulonglong2* pb3 = pb2 + NN;
    float* sedge_w = (float*)(pb3 + NN);       // [EPAD] gcn_norm weights
    u16*   sedge_s = (u16*)(sedge_w + EPAD);   // [EPAD] src byte offsets (slot*16)
    ull*   w1d = (ull*)(sedge_s + EPAD);       // [64 j][4 k] = (W1cat[2k][j], W1cat[2k+1][j])
    float* w2q = (float*)(w1d + 256);          // [32 jp][2 jj][8 c]
    float* b1s = w2q + 512;
    int*   sperm = (int*)(b1s + 64);           // slot -> node
    int*   sptr  = sperm + NN;                 // padded CSR row pointers [NN+1]

    // ---- prepass overlays (dead once staging begins) ----
    float* sdeg = (float*)pb0;                 // [NN]
    int*   scnt = (int*)pb1;                   // [NN]
    int*   sinv = (int*)pb2;                   // [NN] node -> slot
    int*   scur = (int*)pb3;                   // [NN] slot degree / cursor
    int*   hist = (int*)pb0 + 2048;            // [64]
    int*   hoff = hist + 64;                   // [64]
    int*   wsum = hoff + 64;                   // [32]

    const int t  = threadIdx.x;
    const int bs = blockDim.x;
    if (E > EMAXS) return;   // shape guard (never taken for this problem)

    // ================= in-CTA prepass (identical in every CTA) =================
    for (int i = t; i < NN; i += bs) { sdeg[i] = 0.f; scnt[i] = 0; }
    if (t < 64) hist[t] = 0;
    __syncthreads();

    for (int e = t; e < E; e += bs) {
        int c = col[e];
        atomicAdd(&sdeg[c], ew[e]);
        atomicAdd(&scnt[c], 1);
    }
    __syncthreads();

    for (int n = t; n < NN; n += bs) {
        int d = scnt[n]; if (d > 63) d = 63;
        atomicAdd(&hist[d], 1);
    }
    __syncthreads();
    if (t == 0) {
        int run = 0;
        for (int d = 0; d < 64; d++) { hoff[d] = run; run += hist[d]; }
    }
    __syncthreads();

    for (int n = t; n < NN; n += bs) {
        int d = scnt[n]; int dc = (d > 63) ? 63 : d;
        int slot = atomicAdd(&hoff[dc], 1);
        sinv[n] = slot;
        sperm[slot] = n;
        scur[slot] = d;                        // real degree per slot
    }
    __syncthreads();

    {   // exclusive scan of EVEN-PADDED slot-degrees -> sptr; scur = cursors
        int i0 = 2 * t, i1 = 2 * t + 1;
        int a0 = (i0 < NN) ? ((scur[i0] + 1) & ~1) : 0;   // pad to even
        int a1 = (i1 < NN) ? ((scur[i1] + 1) & ~1) : 0;
        int tot = a0 + a1;
        int lane = t & 31, wid = t >> 5;
        int v = tot;
        #pragma unroll
        for (int o = 1; o < 32; o <<= 1) {
            int u = __shfl_up_sync(0xFFFFFFFFu, v, o);
            if (lane >= o) v += u;
        }
        if (lane == 31) wsum[wid] = v;
        __syncthreads();
        if (wid == 0) {
            int w = wsum[lane];
            #pragma unroll
            for (int o = 1; o < 32; o <<= 1) {
                int u = __shfl_up_sync(0xFFFFFFFFu, w, o);
                if (lane >= o) w += u;
            }
            wsum[lane] = w;
        }
        __syncthreads();
        int base = v - tot + (wid ? wsum[wid - 1] : 0);
        if (i0 < NN) sptr[i0] = base;
        if (i1 < NN) sptr[i1] = base + a0;
        if (t == 0)  sptr[NN] = wsum[31];      // padded total
        __syncthreads();
        if (i0 < NN) scur[i0] = sptr[i0];
        if (i1 < NN) scur[i1] = sptr[i1];
    }
    __syncthreads();

    // scatter real edges into padded slot-space CSR
    for (int e = t; e < E; e += bs) {
        int r = row[e], c = col[e];
        float dr = sdeg[r], dc = sdeg[c];
        float ir = (dr > 0.f) ? rsqrtf(dr) : 0.f;
        float ic = (dc > 0.f) ? rsqrtf(dc) : 0.f;
        float nrm = ir * ew[e] * ic;
        int p = atomicAdd(&scur[sinv[c]], 1);
        sedge_s[p] = (u16)(sinv[r] * 16);      // byte offset into ulonglong2 buffer
        sedge_w[p] = nrm;
    }
    __syncthreads();

    // fill <=1 dummy pad edge per node (w=0 -> contributes nothing)
    for (int n = t; n < NN; n += bs) {
        int p = scur[n];
        if (p < sptr[n + 1]) { sedge_s[p] = 0; sedge_w[p] = 0.f; }
    }
    __syncthreads();
    // ================= prepass done; overlays now dead =================

    const int gA = 2 * blockIdx.x;
    int gB = gA + 1; bool hasB = (gB < G); if (!hasB) gB = gA;

    // stage W1 as input-pair packs: w1d[j*4+k] = (W1cat[2k][j], W1cat[2k+1][j])
    for (int i = t; i < 256; i += bs) {
        int j = i >> 2, k = i & 3;
        w1d[i] = pk2(W1[(2 * k) * HID + j], W1[(2 * k + 1) * HID + j]);
    }
    // stage W2 (unchanged layout): w2q[jp*16 + jj*8 + c] = W2cat[2jp+jj][c]
    for (int i = t; i < 512; i += bs) {
        int jp = i >> 4, rem = i & 15;
        int jj = rem >> 3, c = rem & 7;
        int j = 2 * jp + jj;
        w2q[i] = W2[(c >> 1) * (HID * 2) + j * 2 + (c & 1)];
    }
    for (int i = t; i < HID; i += bs) b1s[i] = b1[i];

    // stage x into slot space (permuted gather, both graphs) -> pb0
    const ull* xgA = (const ull*)(x + (size_t)gA * 2 * NN);
    const ull* xgB = (const ull*)(x + (size_t)gB * 2 * NN);
    for (int s = t; s < NN; s += bs) {
        int node = sperm[s];
        pb0[s] = make_ulonglong2(__ldg(&xgA[node]), __ldg(&xgB[node]));
    }
    __syncthreads();

    // ---- gather: u16-pair offsets + f32-pair weights, even length, no tail ----
    #define GATHER(PIN, POUT, ADD, USE_ADD)                                    \
    {   const char* pinc = (const char*)(PIN);                                 \
        _Pragma("unroll 1")                                                    \
        for (int n = t; n < NN; n += bs) {                                     \
            int b = sptr[n], e = sptr[n + 1];                                  \
            ull a0 = 0ull, a1 = 0ull, c0 = 0ull, c1 = 0ull;                    \
            if (USE_ADD) { ulonglong2 z = (ADD)[n]; a0 = z.x; a1 = z.y; }      \
            _Pragma("unroll 1")                                                \
            for (int q = b; q < e; q += 2) {                                   \
                uint32 ss = *(const uint32*)(sedge_s + q);                     \
                float2 wv = *(const float2*)(sedge_w + q);                     \
                ulonglong2 v0 = *(const ulonglong2*)(pinc + (ss & 0xFFFFu));   \
                ulonglong2 v1 = *(const ulonglong2*)(pinc + (ss >> 16));       \
                ull ww0 = pk2(wv.x, wv.x), ww1 = pk2(wv.y, wv.y);              \
                a0 = fma2v(v0.x, ww0, a0); a1 = fma2v(v0.y, ww0, a1);          \
                c0 = fma2v(v1.x, ww1, c0); c1 = fma2v(v1.y, ww1, c1);          \
            }                                                                  \
            a0 = add2v(a0, c0); a1 = add2v(a1, c1);                            \
            (POUT)[n] = make_ulonglong2(a0, a1);                               \
        }                                                                      \
    }

    // layer-1 hops
    GATHER(pb0, pb1, pb0, false); __syncthreads();
    GATHER(pb1, pb2, pb0, false); __syncthreads();
    GATHER(pb2, pb3, pb0, false); __syncthreads();

    // ---- dense per-node sandwich: raw-pair W1, lane-sum h, broadcast W2 ----
    {
        const ulonglong2* w1p = (const ulonglong2*)w1d;   // [64 j][2]
        const ulonglong2* w2v = (const ulonglong2*)w2q;   // [32 jp][4]
        const ull* b1v = (const ull*)b1s;
        #pragma unroll 1
        for (int n = t; n < NN; n += bs) {
            ulonglong2 q0 = pb0[n], q1 = pb1[n], q2 = pb2[n], q3 = pb3[n];
            ull pA0 = q0.x, pB0 = q0.y;   // (hop0 f0, hop0 f1) = inputs (0,1)
            ull pA1 = q1.x, pB1 = q1.y;   // inputs (2,3)
            ull pA2 = q2.x, pB2 = q2.y;   // inputs (4,5)
            ull pA3 = q3.x, pB3 = q3.y;   // inputs (6,7)
            ull mA0 = 0, mA1 = 0, mA2 = 0, mA3 = 0;
            ull mB0 = 0, mB1 = 0, mB2 = 0, mB3 = 0;
            #pragma unroll 4
            for (int jp = 0; jp < 32; jp++) {
                ulonglong2 wa = w1p[4 * jp + 0];   // hidden 2jp   : k=0,1
                ulonglong2 wb = w1p[4 * jp + 1];   // hidden 2jp   : k=2,3
                ulonglong2 wc = w1p[4 * jp + 2];   // hidden 2jp+1 : k=0,1
                ulonglong2 wd = w1p[4 * jp + 3];   // hidden 2jp+1 : k=2,3
                ull sA0 = 0, sA1 = 0, sB0 = 0, sB1 = 0;
                sA0 = fma2v(pA0, wa.x, sA0); sA0 = fma2v(pA1, wa.y, sA0);
                sA0 = fma2v(pA2, wb.x, sA0); sA0 = fma2v(pA3, wb.y, sA0);
                sA1 = fma2v(pA0, wc.x, sA1); sA1 = fma2v(pA1, wc.y, sA1);
                sA1 = fma2v(pA2, wd.x, sA1); sA1 = fma2v(pA3, wd.y, sA1);
                sB0 = fma2v(pB0, wa.x, sB0); sB0 = fma2v(pB1, wa.y, sB0);
                sB0 = fma2v(pB2, wb.x, sB0); sB0 = fma2v(pB3, wb.y, sB0);
                sB1 = fma2v(pB0, wc.x, sB1); sB1 = fma2v(pB1, wc.y, sB1);
                sB1 = fma2v(pB2, wd.x, sB1); sB1 = fma2v(pB3, wd.y, sB1);
                ull bb = b1v[jp];
                float bl, bh; upk2(bb, bl, bh);
                float u0, u1;
                upk2(sA0, u0, u1); float hA0 = fmaxf(u0 + u1 + bl, 0.f);
                upk2(sA1, u0, u1); float hA1 = fmaxf(u0 + u1 + bh, 0.f);
                upk2(sB0, u0, u1); float hB0 = fmaxf(u0 + u1 + bl, 0.f);
                upk2(sB1, u0, u1); float hB1 = fmaxf(u0 + u1 + bh, 0.f);
                ull hA0p = pk2(hA0, hA0), hA1p = pk2(hA1, hA1);
                ull hB0p = pk2(hB0, hB0), hB1p = pk2(hB1, hB1);
                ulonglong2 ra = w2v[jp * 4 + 0], rb = w2v[jp * 4 + 1];
                ulonglong2 rc = w2v[jp * 4 + 2], rd = w2v[jp * 4 + 3];
                mA0 = fma2v(hA0p, ra.x, mA0); mA1 = fma2v(hA0p, ra.y, mA1);
                mA2 = fma2v(hA0p, rb.x, mA2); mA3 = fma2v(hA0p, rb.y, mA3);
                mA0 = fma2v(hA1p, rc.x, mA0); mA1 = fma2v(hA1p, rc.y, mA1);
                mA2 = fma2v(hA1p, rd.x, mA2); mA3 = fma2v(hA1p, rd.y, mA3);
                mB0 = fma2v(hB0p, ra.x, mB0); mB1 = fma2v(hB0p, ra.y, mB1);
                mB2 = fma2v(hB0p, rb.x, mB2); mB3 = fma2v(hB0p, rb.y, mB3);
                mB0 = fma2v(hB1p, rc.x, mB0); mB1 = fma2v(hB1p, rc.y, mB1);
                mB2 = fma2v(hB1p, rd.x, mB2); mB3 = fma2v(hB1p, rd.y, mB3);
            }
            pb0[n] = make_ulonglong2(mA0, mB0);   // m0
            pb1[n] = make_ulonglong2(mA1, mB1);   // m1
            pb2[n] = make_ulonglong2(mA2, mB2);   // m2
            pb3[n] = make_ulonglong2(mA3, mB3);   // m3
        }
    }
    __syncthreads();

    // layer-2 Horner, in-place addends (ADD[n] read only by its owning thread):
    GATHER(pb3, pb2, pb2, true); __syncthreads();   // pb2 <- m2 + A m3
    GATHER(pb2, pb1, pb1, true); __syncthreads();   // pb1 <- m1 + A pb2

    // epilogue: out = x + m0 + A pb1 + b2 (same edge pattern; x reloaded via perm)
    {
        float b20 = b2[0], b21 = b2[1];
        float2* ogA = (float2*)out + (size_t)gA * NN;
        float2* ogB = (float2*)out + (size_t)gB * NN;
        const char* pinc = (const char*)pb1;
        #pragma unroll 1
        for (int n = t; n < NN; n += bs) {
            int node = sperm[n];
            ull xA = __ldg(&xgA[node]);
            ull xB = __ldg(&xgB[node]);
            int b = sptr[n], e = sptr[n + 1];
            ulonglong2 m0 = pb0[n];
            ull a0 = m0.x, a1 = m0.y, c0 = 0ull, c1 = 0ull;
            #pragma unroll 1
            for (int q = b; q < e; q += 2) {
                uint32 ss = *(const uint32*)(sedge_s + q);
                float2 wv = *(const float2*)(sedge_w + q);
                ulonglong2 v0 = *(const ulonglong2*)(pinc + (ss & 0xFFFFu));
                ulonglong2 v1 = *(const ulonglong2*)(pinc + (ss >> 16));
                ull ww0 = pk2(wv.x, wv.x), ww1 = pk2(wv.y, wv.y);
                a0 = fma2v(v0.x, ww0, a0); a1 = fma2v(v0.y, ww0, a1);
                c0 = fma2v(v1.x, ww1, c0); c1 = fma2v(v1.y, ww1, c1);
            }
            a0 = add2v(a0, c0); a1 = add2v(a1, c1);
            float ox, oy, xl, xh;
            upk2(a0, ox, oy); upk2(xA, xl, xh);
            ogA[node] = make_float2(xl + ox + b20, xh + oy + b21);
            if (hasB) {
                upk2(a1, ox, oy); upk2(xB, xl, xh);
                ogB[node] = make_float2(xl + ox + b20, xh + oy + b21);
            }
        }
    }
    #undef GATHER
}

// ---------------- launcher ----------------
extern "C" void kernel_launch(void* const* d_in, const int* in_sizes, int n_in,
                              void* d_out, int out_size) {
    const float* x   = (const float*)d_in[0];
    const int*   row = (const int*)  d_in[1];
    const int*   col = (const int*)  d_in[2];
    const float* ew  = (const float*)d_in[3];
    const float* W1  = (const float*)d_in[4];
    const float* b1  = (const float*)d_in[5];
    const float* W2  = (const float*)d_in[6];
    const float* b2  = (const float*)d_in[7];

    const int E = in_sizes[1];
    const int G = in_sizes[0] / (2 * NN);
    const int nCta = (G + 1) / 2;

    cudaFuncSetAttribute(k_main, cudaFuncAttributeMaxDynamicSharedMemorySize, SMEM_BYTES);

    k_main<<<nCta, TPB, SMEM_BYTES>>>(x, row, col, ew, W1, b1, W2, b2,
                                      (float*)d_out, G, E);
}

// round 17
// speedup vs baseline: 1.0793x; 1.0793x over previous
#include <cuda_runtime.h>
#include <cuda_bf16.h>

// Fixed-shape problem: N=2000 nodes, F=2, HIDDEN=64, K=3, G=256 graphs, E~7998 edges
#define NN    2000
#define EMAXS 8192           // max real edges supported
#define EPAD  10240          // padded capacity (E + <=1 dummy per node)
#define HID   64
#define TPB   1024

typedef unsigned long long ull;
typedef unsigned short u16;
typedef unsigned int uint32;

// ---------------- f32x2 packed-math helpers (sm_100+ PTX) ----------------
__device__ __forceinline__ ull pk2(float lo, float hi) {
    ull r; asm("mov.b64 %0,{%1,%2};" : "=l"(r) : "f"(lo), "f"(hi)); return r;
}
__device__ __forceinline__ void upk2(ull v, float& lo, float& hi) {
    asm("mov.b64 {%0,%1}, %2;" : "=f"(lo), "=f"(hi) : "l"(v));
}
__device__ __forceinline__ ull fma2v(ull a, ull b, ull c) {
    ull d; asm("fma.rn.f32x2 %0, %1, %2, %3;" : "=l"(d) : "l"(a), "l"(b), "l"(c)); return d;
}
__device__ __forceinline__ ull add2v(ull a, ull b) {
    ull d; asm("add.rn.f32x2 %0, %1, %2;" : "=l"(d) : "l"(a), "l"(b)); return d;
}

// ---------------- single fused kernel: one CTA per TWO graphs ----------------
// smem: pb0..pb3 (ulonglong2[NN]) | sedge_w f32[EPAD] | sedge_s u16[EPAD] |
//       w1q/w2q/b1s | sperm | sptr | smeta
// Node buffers: ulonglong2 per node = { graphA pair(f0,f1), graphB pair(f0,f1) }
#define SMEM_BYTES (4 * NN * 16 + EPAD * 4 + EPAD * 2 + 2048 + 2048 + 256 + NN * 4 + (NN + 1) * 4 + NN * 4)

__global__ __launch_bounds__(TPB, 1)
void k_main(const float* __restrict__ x,
            const int* __restrict__ row, const int* __restrict__ col,
            const float* __restrict__ ew,
            const float* __restrict__ W1, const float* __restrict__ b1,
            const float* __restrict__ W2, const float* __restrict__ b2,
            float* __restrict__ out, int G, int E) {
    extern __shared__ float sm[];
    ulonglong2* pb0 = (ulonglong2*)sm;
    ulonglong2* pb1 = pb0 + NN;
    ulonglong2* pb2 = pb1 + NN;
    ulonglong2* pb3 = pb2 + NN;
    float* sedge_w = (float*)(pb3 + NN);       // [EPAD] gcn_norm weights
    u16*   sedge_s = (u16*)(sedge_w + EPAD);   // [EPAD] src byte offsets (slot*16)
    float* w1q = (float*)(sedge_s + EPAD);     // [32 jp][8 i][2 half]
    float* w2q = w1q + 512;                    // [32 jp][2 jj][8 c]
    float* b1s = w2q + 512;
    int*   sperm = (int*)(b1s + 64);           // slot -> node
    int*   sptr  = sperm + NN;                 // padded CSR row pointers [NN+1]
    uint32* smeta = (uint32*)(sptr + NN + 1);  // [NN] begin | (padded_count<<18)

    // ---- prepass overlays (dead once staging begins) ----
    float* sdeg = (float*)pb0;                 // [NN]
    int*   scnt = (int*)pb1;                   // [NN]
    int*   sinv = (int*)pb2;                   // [NN] node -> slot
    int*   scur = (int*)pb3;                   // [NN] slot degree / cursor
    int*   hist = (int*)pb0 + 2048;            // [64]
    int*   hoff = hist + 64;                   // [64]
    int*   wsum = hoff + 64;                   // [32]

    const int t  = threadIdx.x;
    const int bs = blockDim.x;
    if (E > EMAXS) return;   // shape guard (never taken for this problem)

    // ================= in-CTA prepass (identical in every CTA) =================
    for (int i = t; i < NN; i += bs) { sdeg[i] = 0.f; scnt[i] = 0; }
    if (t < 64) hist[t] = 0;
    __syncthreads();

    for (int e = t; e < E; e += bs) {
        int c = col[e];
        atomicAdd(&sdeg[c], ew[e]);
        atomicAdd(&scnt[c], 1);
    }
    __syncthreads();

    for (int n = t; n < NN; n += bs) {
        int d = scnt[n]; if (d > 63) d = 63;
        atomicAdd(&hist[d], 1);
    }
    __syncthreads();
    if (t < 32) {   // warp-parallel exclusive scan over 64 bins (2 per lane)
        int h0 = hist[2 * t], h1 = hist[2 * t + 1];
        int s = h0 + h1;
        int v = s;
        #pragma unroll
        for (int o = 1; o < 32; o <<= 1) {
            int u = __shfl_up_sync(0xFFFFFFFFu, v, o);
            if (t >= o) v += u;
        }
        int base = v - s;
        hoff[2 * t] = base; hoff[2 * t + 1] = base + h0;
    }
    __syncthreads();

    for (int n = t; n < NN; n += bs) {
        int d = scnt[n]; int dc = (d > 63) ? 63 : d;
        int slot = atomicAdd(&hoff[dc], 1);
        sinv[n] = slot;
        sperm[slot] = n;
        scur[slot] = d;                        // real degree per slot
    }
    __syncthreads();

    {   // exclusive scan of EVEN-PADDED slot-degrees -> sptr + smeta; scur = cursors
        int i0 = 2 * t, i1 = 2 * t + 1;
        int a0 = (i0 < NN) ? ((scur[i0] + 1) & ~1) : 0;   // pad to even
        int a1 = (i1 < NN) ? ((scur[i1] + 1) & ~1) : 0;
        int tot = a0 + a1;
        int lane = t & 31, wid = t >> 5;
        int v = tot;
        #pragma unroll
        for (int o = 1; o < 32; o <<= 1) {
            int u = __shfl_up_sync(0xFFFFFFFFu, v, o);
            if (lane >= o) v += u;
        }
        if (lane == 31) wsum[wid] = v;
        __syncthreads();
        if (wid == 0) {
            int w = wsum[lane];
            #pragma unroll
            for (int o = 1; o < 32; o <<= 1) {
                int u = __shfl_up_sync(0xFFFFFFFFu, w, o);
                if (lane >= o) w += u;
            }
            wsum[lane] = w;
        }
        __syncthreads();
        int base = v - tot + (wid ? wsum[wid - 1] : 0);
        if (i0 < NN) { sptr[i0] = base;      smeta[i0] = (uint32)base | ((uint32)a0 << 18); }
        if (i1 < NN) { sptr[i1] = base + a0; smeta[i1] = (uint32)(base + a0) | ((uint32)a1 << 18); }
        if (t == 0)  sptr[NN] = wsum[31];      // padded total
        __syncthreads();
        if (i0 < NN) scur[i0] = sptr[i0];
        if (i1 < NN) scur[i1] = sptr[i1];
    }
    __syncthreads();

    // scatter real edges into padded slot-space CSR
    for (int e = t; e < E; e += bs) {
        int r = row[e], c = col[e];
        float dr = sdeg[r], dc = sdeg[c];
        float ir = (dr > 0.f) ? rsqrtf(dr) : 0.f;
        float ic = (dc > 0.f) ? rsqrtf(dc) : 0.f;
        float nrm = ir * ew[e] * ic;
        int p = atomicAdd(&scur[sinv[c]], 1);
        sedge_s[p] = (u16)(sinv[r] * 16);      // byte offset into ulonglong2 buffer
        sedge_w[p] = nrm;
    }
    __syncthreads();

    // fill <=1 dummy pad edge per node (w=0 -> contributes nothing)
    for (int n = t; n < NN; n += bs) {
        int p = scur[n];
        if (p < sptr[n + 1]) { sedge_s[p] = 0; sedge_w[p] = 0.f; }
    }
    __syncthreads();
    // ================= prepass done; overlays now dead =================

    const int gA = 2 * blockIdx.x;
    int gB = gA + 1; bool hasB = (gB < G); if (!hasB) gB = gA;

    // stage packed weights (R15 layout)
    for (int i = t; i < 512; i += bs) {
        int jp = i >> 4, rem = i & 15;
        {   int ii = rem >> 1, half = rem & 1;
            w1q[i] = W1[ii * HID + 2 * jp + half]; }
        {   int jj = rem >> 3, c = rem & 7;
            int j = 2 * jp + jj;
            w2q[i] = W2[(c >> 1) * (HID * 2) + j * 2 + (c & 1)]; }
    }
    for (int i = t; i < HID; i += bs) b1s[i] = b1[i];

    // stage x into slot space (permuted gather, both graphs) -> pb0
    const ull* xgA = (const ull*)(x + (size_t)gA * 2 * NN);
    const ull* xgB = (const ull*)(x + (size_t)gB * 2 * NN);
    for (int s = t; s < NN; s += bs) {
        int node = sperm[s];
        pb0[s] = make_ulonglong2(__ldg(&xgA[node]), __ldg(&xgB[node]));
    }
    __syncthreads();

    // ---- gather: packed meta, u16-pair offsets + f32-pair weights, even length ----
    #define GATHER(PIN, POUT, ADD, USE_ADD)                                    \
    {   const char* pinc = (const char*)(PIN);                                 \
        _Pragma("unroll 1")                                                    \
        for (int n = t; n < NN; n += bs) {                                     \
            uint32 mt = smeta[n];                                              \
            int b = (int)(mt & 0x3FFFFu);                                      \
            int e = b + (int)(mt >> 18);                                       \
            ull a0 = 0ull, a1 = 0ull, c0 = 0ull, c1 = 0ull;                    \
            if (USE_ADD) { ulonglong2 z = (ADD)[n]; a0 = z.x; a1 = z.y; }      \
            _Pragma("unroll 1")                                                \
            for (int q = b; q < e; q += 2) {                                   \
                uint32 ss = *(const uint32*)(sedge_s + q);                     \
                float2 wv = *(const float2*)(sedge_w + q);                     \
                ulonglong2 v0 = *(const ulonglong2*)(pinc + (ss & 0xFFFFu));   \
                ulonglong2 v1 = *(const ulonglong2*)(pinc + (ss >> 16));       \
                ull ww0 = pk2(wv.x, wv.x), ww1 = pk2(wv.y, wv.y);              \
                a0 = fma2v(v0.x, ww0, a0); a1 = fma2v(v0.y, ww0, a1);          \
                c0 = fma2v(v1.x, ww1, c0); c1 = fma2v(v1.y, ww1, c1);          \
            }                                                                  \
            a0 = add2v(a0, c0); a1 = add2v(a1, c1);                            \
            (POUT)[n] = make_ulonglong2(a0, a1);                               \
        }                                                                      \
    }

    // layer-1 hops
    GATHER(pb0, pb1, pb0, false); __syncthreads();
    GATHER(pb1, pb2, pb0, false); __syncthreads();
    GATHER(pb2, pb3, pb0, false); __syncthreads();

    // ---- dense per-node sandwich (verbatim R15): [8] -> 64 (relu) -> [8] ----
    {
        const ulonglong2* w1v = (const ulonglong2*)w1q;
        const ulonglong2* w2v = (const ulonglong2*)w2q;
        const ull* b1v = (const ull*)b1s;
        for (int n = t; n < NN; n += bs) {
            ulonglong2 a0 = pb0[n], a1 = pb1[n], a2 = pb2[n], a3 = pb3[n];
            float f0, f1;
            upk2(a0.x, f0, f1); ull pA0 = pk2(f0, f0), pA1 = pk2(f1, f1);
            upk2(a1.x, f0, f1); ull pA2 = pk2(f0, f0), pA3 = pk2(f1, f1);
            upk2(a2.x, f0, f1); ull pA4 = pk2(f0, f0), pA5 = pk2(f1, f1);
            upk2(a3.x, f0, f1); ull pA6 = pk2(f0, f0), pA7 = pk2(f1, f1);
            upk2(a0.y, f0, f1); ull pB0 = pk2(f0, f0), pB1 = pk2(f1, f1);
            upk2(a1.y, f0, f1); ull pB2 = pk2(f0, f0), pB3 = pk2(f1, f1);
            upk2(a2.y, f0, f1); ull pB4 = pk2(f0, f0), pB5 = pk2(f1, f1);
            upk2(a3.y, f0, f1); ull pB6 = pk2(f0, f0), pB7 = pk2(f1, f1);
            ull mA0 = 0, mA1 = 0, mA2 = 0, mA3 = 0;
            ull mB0 = 0, mB1 = 0, mB2 = 0, mB3 = 0;
            #pragma unroll 4
            for (int jp = 0; jp < 32; jp++) {
                ulonglong2 qa = w1v[jp * 4 + 0], qb = w1v[jp * 4 + 1];
                ulonglong2 qc = w1v[jp * 4 + 2], qd = w1v[jp * 4 + 3];
                ull bb = b1v[jp];
                ull hA = bb, hB = bb;
                hA = fma2v(pA0, qa.x, hA); hA = fma2v(pA1, qa.y, hA);
                hA = fma2v(pA2, qb.x, hA); hA = fma2v(pA3, qb.y, hA);
                hA = fma2v(pA4, qc.x, hA); hA = fma2v(pA5, qc.y, hA);
                hA = fma2v(pA6, qd.x, hA); hA = fma2v(pA7, qd.y, hA);
                hB = fma2v(pB0, qa.x, hB); hB = fma2v(pB1, qa.y, hB);
                hB = fma2v(pB2, qb.x, hB); hB = fma2v(pB3, qb.y, hB);
                hB = fma2v(pB4, qc.x, hB); hB = fma2v(pB5, qc.y, hB);
                hB = fma2v(pB6, qd.x, hB); hB = fma2v(pB7, qd.y, hB);
                float hA0, hA1, hB0, hB1;
                upk2(hA, hA0, hA1); upk2(hB, hB0, hB1);
                hA0 = fmaxf(hA0, 0.f); hA1 = fmaxf(hA1, 0.f);
                hB0 = fmaxf(hB0, 0.f); hB1 = fmaxf(hB1, 0.f);
                ull hA0p = pk2(hA0, hA0), hA1p = pk2(hA1, hA1);
                ull hB0p = pk2(hB0, hB0), hB1p = pk2(hB1, hB1);
                ulonglong2 ra = w2v[jp * 4 + 0], rb = w2v[jp * 4 + 1];
                ulonglong2 rc = w2v[jp * 4 + 2], rd = w2v[jp * 4 + 3];
                mA0 = fma2v(hA0p, ra.x, mA0); mA1 = fma2v(hA0p, ra.y, mA1);
                mA2 = fma2v(hA0p, rb.x, mA2); mA3 = fma2v(hA0p, rb.y, mA3);
                mA0 = fma2v(hA1p, rc.x, mA0); mA1 = fma2v(hA1p, rc.y, mA1);
                mA2 = fma2v(hA1p, rd.x, mA2); mA3 = fma2v(hA1p, rd.y, mA3);
                mB0 = fma2v(hB0p, ra.x, mB0); mB1 = fma2v(hB0p, ra.y, mB1);
                mB2 = fma2v(hB0p, rb.x, mB2); mB3 = fma2v(hB0p, rb.y, mB3);
                mB0 = fma2v(hB1p, rc.x, mB0); mB1 = fma2v(hB1p, rc.y, mB1);
                mB2 = fma2v(hB1p, rd.x, mB2); mB3 = fma2v(hB1p, rd.y, mB3);
            }
            pb0[n] = make_ulonglong2(mA0, mB0);   // m0
            pb1[n] = make_ulonglong2(mA1, mB1);   // m1
            pb2[n] = make_ulonglong2(mA2, mB2);   // m2
            pb3[n] = make_ulonglong2(mA3, mB3);   // m3
        }
    }
    __syncthreads();

    // layer-2 Horner, in-place addends (ADD[n] read only by its owning thread):
    GATHER(pb3, pb2, pb2, true); __syncthreads();   // pb2 <- m2 + A m3
    GATHER(pb2, pb1, pb1, true); __syncthreads();   // pb1 <- m1 + A pb2

    // epilogue: out = x + m0 + A pb1 + b2 (same edge pattern; x reloaded via perm)
    {
        float b20 = b2[0], b21 = b2[1];
        float2* ogA = (float2*)out + (size_t)gA * NN;
        float2* ogB = (float2*)out + (size_t)gB * NN;
        const char* pinc = (const char*)pb1;
        #pragma unroll 1
        for (int n = t; n < NN; n += bs) {
            int node = sperm[n];
            ull xA = __ldg(&xgA[node]);
            ull xB = __ldg(&xgB[node]);
            uint32 mt = smeta[n];
            int b = (int)(mt & 0x3FFFFu);
            int e = b + (int)(mt >> 18);
            ulonglong2 m0 = pb0[n];
            ull a0 = m0.x, a1 = m0.y, c0 = 0ull, c1 = 0ull;
            #pragma unroll 1
            for (int q = b; q < e; q += 2) {
                uint32 ss = *(const uint32*)(sedge_s + q);
                float2 wv = *(const float2*)(sedge_w + q);
                ulonglong2 v0 = *(const ulonglong2*)(pinc + (ss & 0xFFFFu));
                ulonglong2 v1 = *(const ulonglong2*)(pinc + (ss >> 16));
                ull ww0 = pk2(wv.x, wv.x), ww1 = pk2(wv.y, wv.y);
                a0 = fma2v(v0.x, ww0, a0); a1 = fma2v(v0.y, ww0, a1);
                c0 = fma2v(v1.x, ww1, c0); c1 = fma2v(v1.y, ww1, c1);
            }
            a0 = add2v(a0, c0); a1 = add2v(a1, c1);
            float ox, oy, xl, xh;
            upk2(a0, ox, oy); upk2(xA, xl, xh);
            ogA[node] = make_float2(xl + ox + b20, xh + oy + b21);
            if (hasB) {
                upk2(a1, ox, oy); upk2(xB, xl, xh);
                ogB[node] = make_float2(xl + ox + b20, xh + oy + b21);
            }
        }
    }
    #undef GATHER
}

// ---------------- launcher ----------------
extern "C" void kernel_launch(void* const* d_in, const int* in_sizes, int n_in,
                              void* d_out, int out_size) {
    const float* x   = (const float*)d_in[0];
    const int*   row = (const int*)  d_in[1];
    const int*   col = (const int*)  d_in[2];
    const float* ew  = (const float*)d_in[3];
    const float* W1  = (const float*)d_in[4];
    const float* b1  = (const float*)d_in[5];
    const float* W2  = (const float*)d_in[6];
    const float* b2  = (const float*)d_in[7];

    const int E = in_sizes[1];
    const int G = in_sizes[0] / (2 * NN);
    const int nCta = (G + 1) / 2;

    cudaFuncSetAttribute(k_main, cudaFuncAttributeMaxDynamicSharedMemorySize, SMEM_BYTES);

    k_main<<<nCta, TPB, SMEM_BYTES>>>(x, row, col, ew, W1, b1, W2, b2,
                                      (float*)d_out, G, E);
}